// round 7
// baseline (speedup 1.0000x reference)
#include <cuda_runtime.h>
#include <cuda_bf16.h>
#include <cstdint>

// ============================ problem constants ============================
#define BB   64
#define LL   12
#define NN   883
#define DD   64
#define TT   12
#define MM   64
#define ROWS     (BB*NN)        // 56512
#define ROWS_PAD (884*64)       // 56576

// ============================ scratch ======================================
// xs splits, row-major [row][64] bf16 (u32-packed pairs, low half = lower d)
__device__ __nv_bfloat16 g_xs_hi[ROWS_PAD * DD];
__device__ __nv_bfloat16 g_xs_lo[ROWS_PAD * DD];
// Pre-swizzled B fragments for mma.m16n8k16 (row.col), lane-indexed:
//   index = (((t*2 + v)*8 + j)*4 + kk)*32 + lane   (v: 0=hi split, 1=lo split)
//   .x = pack(e_k, e_k+1), .y = pack(e_k+8, e_k+9)  for n = 8j + lane/4, k = 16kk + 2*(lane%4)
// GEMM1: B[k=d][n=m] = M[t][m][d]   GEMM2: B[k=m][n=d] = M[t][m][d]
__device__ uint2 g_Bf1[TT * 2 * 8 * 4 * 32];
__device__ uint2 g_Bf2[TT * 2 * 8 * 4 * 32];

// ============================ helpers ======================================
__device__ __forceinline__ uint32_t pack_bf16(__nv_bfloat16 lo, __nv_bfloat16 hi) {
    return (uint32_t)__bfloat16_as_ushort(lo) | ((uint32_t)__bfloat16_as_ushort(hi) << 16);
}
__device__ __forceinline__ void split_bf16(float v, __nv_bfloat16& h, __nv_bfloat16& l) {
    h = __float2bfloat16_rn(v);
    l = __float2bfloat16_rn(v - __bfloat162float(h));
}
// D += A * B  (m16n8k16, bf16 in, fp32 accum)
__device__ __forceinline__ void mma_bf16(float* c, const uint32_t* a,
                                         uint32_t b0, uint32_t b1) {
    asm volatile(
        "mma.sync.aligned.m16n8k16.row.col.f32.bf16.bf16.f32 "
        "{%0,%1,%2,%3}, {%4,%5,%6,%7}, {%8,%9}, {%0,%1,%2,%3};"
        : "+f"(c[0]), "+f"(c[1]), "+f"(c[2]), "+f"(c[3])
        : "r"(a[0]), "r"(a[1]), "r"(a[2]), "r"(a[3]), "r"(b0), "r"(b1));
}

// ======================= kernel 1: reduce + split + B tables ===============
// blocks [0, 3532): xs[row,d] = sum_l x[b,l,n,d] -> bf16 hi/lo splits
// blocks [3532, 3724): build lane-indexed B fragment tables from M
__global__ __launch_bounds__(256) void ma_prep(const float* __restrict__ x,
                                               const float* __restrict__ Mw) {
    if (blockIdx.x < 3532u) {
        int tid = threadIdx.x;
        int row = blockIdx.x * 16 + (tid >> 4);      // 0..56511 exact
        int d4  = (tid & 15) * 4;
        int b = row / NN;
        int n = row - b * NN;
        const float* base = x + ((size_t)b * LL * NN + n) * DD + d4;
        float4 acc = make_float4(0.f, 0.f, 0.f, 0.f);
#pragma unroll
        for (int l = 0; l < LL; l++) {
            float4 v = *reinterpret_cast<const float4*>(base + (size_t)l * NN * DD);
            acc.x += v.x; acc.y += v.y; acc.z += v.z; acc.w += v.w;
        }
        float a[4] = {acc.x, acc.y, acc.z, acc.w};
        uint32_t hw[2], lw[2];
#pragma unroll
        for (int p = 0; p < 2; p++) {
            __nv_bfloat16 h0, l0, h1, l1;
            split_bf16(a[2*p],   h0, l0);
            split_bf16(a[2*p+1], h1, l1);
            hw[p] = pack_bf16(h0, h1);
            lw[p] = pack_bf16(l0, l1);
        }
        uint32_t* dh = reinterpret_cast<uint32_t*>(g_xs_hi + (size_t)row * DD + d4);
        uint32_t* dl = reinterpret_cast<uint32_t*>(g_xs_lo + (size_t)row * DD + d4);
        dh[0] = hw[0]; dh[1] = hw[1];
        dl[0] = lw[0]; dl[1] = lw[1];
    } else {
        // one thread per uint2 fragment word: 12t * 2g * 2v * 8j * 4kk * 32lane = 49152
        int i = (blockIdx.x - 3532) * 256 + threadIdx.x;
        int lane =  i        & 31;
        int kk   = (i >> 5)  & 3;
        int j    = (i >> 7)  & 7;
        int v    = (i >> 10) & 1;
        int g    = (i >> 11) & 1;
        int t    =  i >> 12;
        int nidx = 8 * j + (lane >> 2);          // fragment column
        int kbase = 16 * kk + 2 * (lane & 3);    // fragment row (k)
        const float* Mt = Mw + t * (MM * DD);
        float e0, e1, e2, e3;
        if (g == 0) {   // GEMM1: B[k=d][n=m] = M[m][d]
            int m = nidx;
            e0 = Mt[m * DD + kbase];
            e1 = Mt[m * DD + kbase + 1];
            e2 = Mt[m * DD + kbase + 8];
            e3 = Mt[m * DD + kbase + 9];
        } else {        // GEMM2: B[k=m][n=d] = M[m][d]
            int d = nidx;
            e0 = Mt[(kbase    ) * DD + d];
            e1 = Mt[(kbase + 1) * DD + d];
            e2 = Mt[(kbase + 8) * DD + d];
            e3 = Mt[(kbase + 9) * DD + d];
        }
        __nv_bfloat16 h, l;
        __nv_bfloat16 f0, f1, f2, f3;
        split_bf16(e0, h, l); f0 = v ? l : h;
        split_bf16(e1, h, l); f1 = v ? l : h;
        split_bf16(e2, h, l); f2 = v ? l : h;
        split_bf16(e3, h, l); f3 = v ? l : h;
        uint2 w = make_uint2(pack_bf16(f0, f1), pack_bf16(f2, f3));
        int idx = (((t * 2 + v) * 8 + j) * 4 + kk) * 32 + lane;
        if (g == 0) g_Bf1[idx] = w; else g_Bf2[idx] = w;
    }
}

// ======================= kernel 2: GEMM-softmax-GEMM (HMMA) ================
// 128 threads = 4 warps; warp w owns rows [blk*64 + 16w, +16). 884 blocks.
__global__ __launch_bounds__(128) void ma_main(float* __restrict__ out) {
    int tid  = threadIdx.x;
    int wid  = tid >> 5;
    int lane = tid & 31;
    int qr   = lane >> 2;        // fragment row within tile (0..7)
    int qc   = lane & 3;         // k/col group (0..3)

    int row0 = blockIdx.x * 64 + wid * 16;
    int rA = row0 + qr;
    int rB = rA + 8;
    bool vA = rA < ROWS;
    bool vB = rB < ROWS;
    int rAc = vA ? rA : (ROWS - 1);
    int rBc = vB ? rB : (ROWS - 1);
    int bA = rAc / NN, nA = rAc - bA * NN;
    int bcl = rBc / NN, nB = rBc - bcl * NN;
    size_t oA = ((size_t)bA  * TT * NN + nA) * DD;
    size_t oB = ((size_t)bcl * TT * NN + nB) * DD;

    // ---- A fragments (xs splits) live in registers for all 12 t ----
    uint32_t ah[16], al[16];
    {
        const uint32_t* xh = reinterpret_cast<const uint32_t*>(g_xs_hi);
        const uint32_t* xl = reinterpret_cast<const uint32_t*>(g_xs_lo);
        int baseA = rA * 32, baseB = rB * 32;   // rows < ROWS_PAD always
#pragma unroll
        for (int kk = 0; kk < 4; kk++) {
            int o = 8 * kk + qc;
            ah[4*kk+0] = xh[baseA + o];     ah[4*kk+1] = xh[baseB + o];
            ah[4*kk+2] = xh[baseA + o + 4]; ah[4*kk+3] = xh[baseB + o + 4];
            al[4*kk+0] = xl[baseA + o];     al[4*kk+1] = xl[baseB + o];
            al[4*kk+2] = xl[baseA + o + 4]; al[4*kk+3] = xl[baseB + o + 4];
        }
    }

    for (int t = 0; t < TT; t++) {
        float acc[32];
#pragma unroll
        for (int i = 0; i < 32; i++) acc[i] = 0.f;

        // ---- GEMM1: scores = xs @ M^T, 3-pass split bf16 ----
        {
            const uint2* Bh = g_Bf1 + (size_t)(t * 2    ) * 8 * 4 * 32 + lane;
            const uint2* Bl = g_Bf1 + (size_t)(t * 2 + 1) * 8 * 4 * 32 + lane;
#pragma unroll
            for (int pass = 0; pass < 3; pass++) {
                const uint32_t* A  = (pass == 1) ? al : ah;
                const uint2*    Bp = (pass == 2) ? Bl : Bh;
#pragma unroll
                for (int kk = 0; kk < 4; kk++)
#pragma unroll
                    for (int j = 0; j < 8; j++) {
                        uint2 b = Bp[(j * 4 + kk) * 32];
                        mma_bf16(&acc[4*j], A + 4*kk, b.x, b.y);
                    }
            }
        }

        // ---- softmax over 64 m (rows split across 4-lane quads) ----
        float mA = -1e30f, mB = -1e30f;
#pragma unroll
        for (int j = 0; j < 8; j++) {
            mA = fmaxf(mA, fmaxf(acc[4*j],   acc[4*j+1]));
            mB = fmaxf(mB, fmaxf(acc[4*j+2], acc[4*j+3]));
        }
        mA = fmaxf(mA, __shfl_xor_sync(0xffffffffu, mA, 1));
        mA = fmaxf(mA, __shfl_xor_sync(0xffffffffu, mA, 2));
        mB = fmaxf(mB, __shfl_xor_sync(0xffffffffu, mB, 1));
        mB = fmaxf(mB, __shfl_xor_sync(0xffffffffu, mB, 2));
        float sA = 0.f, sB = 0.f;
#pragma unroll
        for (int j = 0; j < 8; j++) {
            acc[4*j]   = __expf(acc[4*j]   - mA);
            acc[4*j+1] = __expf(acc[4*j+1] - mA);
            acc[4*j+2] = __expf(acc[4*j+2] - mB);
            acc[4*j+3] = __expf(acc[4*j+3] - mB);
            sA += acc[4*j] + acc[4*j+1];
            sB += acc[4*j+2] + acc[4*j+3];
        }
        sA += __shfl_xor_sync(0xffffffffu, sA, 1);
        sA += __shfl_xor_sync(0xffffffffu, sA, 2);
        sB += __shfl_xor_sync(0xffffffffu, sB, 1);
        sB += __shfl_xor_sync(0xffffffffu, sB, 2);
        float iA = 1.0f / sA, iB = 1.0f / sB;

        // ---- p -> A fragments (C layout == A layout; split hi/lo) ----
        uint32_t pah[16], pal[16];
#pragma unroll
        for (int kk = 0; kk < 4; kk++) {
            int j0 = 2 * kk, j1 = 2 * kk + 1;
            float p00 = acc[4*j0]   * iA, p01 = acc[4*j0+1] * iA;
            float p02 = acc[4*j0+2] * iB, p03 = acc[4*j0+3] * iB;
            float p10 = acc[4*j1]   * iA, p11 = acc[4*j1+1] * iA;
            float p12 = acc[4*j1+2] * iB, p13 = acc[4*j1+3] * iB;
            __nv_bfloat16 h0,l0,h1,l1;
            split_bf16(p00, h0, l0); split_bf16(p01, h1, l1);
            pah[4*kk+0] = pack_bf16(h0, h1); pal[4*kk+0] = pack_bf16(l0, l1);
            split_bf16(p02, h0, l0); split_bf16(p03, h1, l1);
            pah[4*kk+1] = pack_bf16(h0, h1); pal[4*kk+1] = pack_bf16(l0, l1);
            split_bf16(p10, h0, l0); split_bf16(p11, h1, l1);
            pah[4*kk+2] = pack_bf16(h0, h1); pal[4*kk+2] = pack_bf16(l0, l1);
            split_bf16(p12, h0, l0); split_bf16(p13, h1, l1);
            pah[4*kk+3] = pack_bf16(h0, h1); pal[4*kk+3] = pack_bf16(l0, l1);
        }

        // ---- GEMM2: value = p @ M, 3-pass split bf16 ----
#pragma unroll
        for (int i = 0; i < 32; i++) acc[i] = 0.f;
        {
            const uint2* Bh = g_Bf2 + (size_t)(t * 2    ) * 8 * 4 * 32 + lane;
            const uint2* Bl = g_Bf2 + (size_t)(t * 2 + 1) * 8 * 4 * 32 + lane;
#pragma unroll
            for (int pass = 0; pass < 3; pass++) {
                const uint32_t* A  = (pass == 1) ? pal : pah;
                const uint2*    Bp = (pass == 2) ? Bl : Bh;
#pragma unroll
                for (int kk = 0; kk < 4; kk++)
#pragma unroll
                    for (int j = 0; j < 8; j++) {
                        uint2 b = Bp[(j * 4 + kk) * 32];
                        mma_bf16(&acc[4*j], A + 4*kk, b.x, b.y);
                    }
            }
        }

        // ---- store value tile ----
        size_t tofs = (size_t)t * (NN * DD);
        if (vA) {
            float* po = out + oA + tofs + 2 * qc;
#pragma unroll
            for (int j = 0; j < 8; j++)
                *reinterpret_cast<float2*>(po + 8 * j) = make_float2(acc[4*j], acc[4*j+1]);
        }
        if (vB) {
            float* po = out + oB + tofs + 2 * qc;
#pragma unroll
            for (int j = 0; j < 8; j++)
                *reinterpret_cast<float2*>(po + 8 * j) = make_float2(acc[4*j+2], acc[4*j+3]);
        }
    }
}

// ============================ launch =======================================
extern "C" void kernel_launch(void* const* d_in, const int* in_sizes, int n_in,
                              void* d_out, int out_size) {
    const float* x  = (const float*)d_in[0];
    const float* Mw = (const float*)d_in[1];
    float* out = (float*)d_out;

    ma_prep<<<3724, 256>>>(x, Mw);   // 3532 xs blocks + 192 B-table blocks
    ma_main<<<884, 128>>>(out);
}